// round 15
// baseline (speedup 1.0000x reference)
#include <cuda_runtime.h>
#include <cuda_bf16.h>
#include <cuda_fp16.h>
#include <cstdint>

#define EPSV 1e-5f
#define B_   4
#define C_   96
#define HW   4096
#define OCT  166     // 18 + 50 + 98 offset channels
#define OCP  192     // weight-pack padding
#define KOF  864     // 9*96 offset-conv K
#define KP   320     // g_xc row stride (288 used)
#define O_   192

// ---------------- scratch (static device globals) -----------------------------
__device__ float g_off[B_ * OCT * HW];          // offset conv output  [b][oc][p]
__device__ float g_xc [B_ * HW * KP];           // deform output, PIXEL-major [b*HW+p][KP]
__device__ float g_bo [OCP];                    // packed offset bias
__device__ __nv_bfloat16 g_xth[B_ * HW * 96];   // x transposed hi [b*HW+p][c]
__device__ __nv_bfloat16 g_xtl[B_ * HW * 96];   // x transposed lo
__device__ __nv_bfloat16 g_wofh[OCP * KOF];     // offset weights hi [oc][tap*96+c]
__device__ __nv_bfloat16 g_wofl[OCP * KOF];     // offset weights lo
__device__ __nv_bfloat16 g_pwh[O_ * KP];        // pointwise weights hi [o][KP]
__device__ __nv_bfloat16 g_pwl[O_ * KP];        // pointwise weights lo [o][KP]

__device__ __forceinline__ uint32_t smem_u32(const void* p) {
    uint32_t a;
    asm("{ .reg .u64 t; cvta.to.shared.u64 t, %1; cvt.u32.u64 %0, t; }" : "=r"(a) : "l"(p));
    return a;
}
#define LDSM4(r, addr) \
    asm volatile("ldmatrix.sync.aligned.m8n8.x4.shared.b16 {%0,%1,%2,%3}, [%4];" \
        : "=r"((r)[0]), "=r"((r)[1]), "=r"((r)[2]), "=r"((r)[3]) : "r"(addr))
#define LDSM2(r, addr) \
    asm volatile("ldmatrix.sync.aligned.m8n8.x2.shared.b16 {%0,%1}, [%2];" \
        : "=r"((r)[0]), "=r"((r)[1]) : "r"(addr))
#define MMA_BF16(d, a, b) \
    asm volatile("mma.sync.aligned.m16n8k16.row.col.f32.bf16.bf16.f32 " \
        "{%0,%1,%2,%3}, {%4,%5,%6,%7}, {%8,%9}, {%0,%1,%2,%3};" \
        : "+f"((d)[0]), "+f"((d)[1]), "+f"((d)[2]), "+f"((d)[3]) \
        : "r"((a)[0]), "r"((a)[1]), "r"((a)[2]), "r"((a)[3]), "r"((b)[0]), "r"((b)[1]))
#define CP_ASYNC16(dst, src, n) \
    asm volatile("cp.async.cg.shared.global [%0], [%1], 16, %2;" \
        :: "r"(dst), "l"(src), "r"(n))
#define CP_COMMIT() asm volatile("cp.async.commit_group;" ::: "memory")
#define CP_WAIT(N)  asm volatile("cp.async.wait_group %0;" :: "n"(N) : "memory")

// ---------------- prep: pack + bf16-split weights -----------------------------
__global__ void prep_kernel(const float* __restrict__ w3, const float* __restrict__ b3,
                            const float* __restrict__ w5, const float* __restrict__ b5,
                            const float* __restrict__ w7, const float* __restrict__ b7,
                            const float* __restrict__ wpw) {
    int i0 = blockIdx.x * blockDim.x + threadIdx.x;
    int stride = gridDim.x * blockDim.x;
    for (int idx = i0; idx < OCP * KOF; idx += stride) {
        int oc = idx / KOF, k = idx % KOF;
        int r = k / 96, c = k % 96;
        float v = 0.f;
        if (oc < 18)        v = w3[(oc * C_ + c) * 9 + r];
        else if (oc < 68)   v = w5[((oc - 18) * C_ + c) * 9 + r];
        else if (oc < OCT)  v = w7[((oc - 68) * C_ + c) * 9 + r];
        __nv_bfloat16 h = __float2bfloat16(v);
        g_wofh[idx] = h;
        g_wofl[idx] = __float2bfloat16(v - __bfloat162float(h));
    }
    for (int idx = i0; idx < OCP; idx += stride) {
        float v = 0.f;
        if (idx < 18)       v = b3[idx];
        else if (idx < 68)  v = b5[idx - 18];
        else if (idx < OCT) v = b7[idx - 68];
        g_bo[idx] = v;
    }
    for (int idx = i0; idx < O_ * KP; idx += stride) {
        int n = idx / KP, k = idx % KP;
        float w = (k < 288) ? wpw[n * 288 + k] : 0.f;
        __nv_bfloat16 h = __float2bfloat16(w);
        g_pwh[idx] = h;
        g_pwl[idx] = __float2bfloat16(w - __bfloat162float(h));
    }
}

// ---------------- xpose: x [b][c][p] -> pixel-major bf16 hi/lo (coalesced) -----
__global__ __launch_bounds__(256) void xpose_kernel(const float* __restrict__ x) {
    __shared__ float st[64][97];
    int tid = threadIdx.x;
    int g0 = blockIdx.x * 64;              // global pixel index (b*HW+p)
    int b = g0 >> 12, p0 = g0 & 4095;
    const float* src = x + (size_t)b * C_ * HW + p0;
    for (int i = tid; i < 96 * 64; i += 256) {
        int c = i >> 6, px = i & 63;
        st[px][c] = src[(size_t)c * HW + px];
    }
    __syncthreads();
    for (int i = tid; i < 64 * 12; i += 256) {
        int px = i / 12, seg = i - px * 12;
        __nv_bfloat16 h8[8], l8[8];
#pragma unroll
        for (int j = 0; j < 8; ++j) {
            float v = st[px][seg * 8 + j];
            h8[j] = __float2bfloat16(v);
            l8[j] = __float2bfloat16(v - __bfloat162float(h8[j]));
        }
        size_t o = (size_t)(g0 + px) * 96 + seg * 8;
        *(uint4*)(g_xth + o) = *(uint4*)h8;
        *(uint4*)(g_xtl + o) = *(uint4*)l8;
    }
}

// ---------------- K1: offset conv, HMMA implicit GEMM, N-split for 2 CTA/SM ----
// grid (32 pixel-tiles, 2 n-groups, 4 batch) = 256 blocks, 256 threads.
// y=0: oc 0..95 (N=96); y=1: oc 96..167 (N=72). K chunk = 48 ch, dbl-buffered.
#define OST   56                           // bf16 per smem row (112 B)
#define OA_SZ 14336                        // one A buf half (128*56*2)
#define OB_SZ 10752                        // one B buf half (96*56*2, max)
#define AB(s)  ((s) * 2 * OA_SZ)
#define BB(s)  (4 * OA_SZ + (s) * 2 * OB_SZ)
#define OFF_SMEM (4 * OA_SZ + 4 * OB_SZ)   // 100352

__global__ __launch_bounds__(256) void offconv_mma_kernel() {
    extern __shared__ char dsm[];
    uint32_t sbase = smem_u32(dsm);
    int tid = threadIdx.x, w = tid >> 5, lane = tid & 31;
    int m0 = (w & 3) * 32;
    int ng = w >> 2;
    int yb = blockIdx.y;
    int NBASE = yb * 96;
    int NB = yb ? 72 : 96;                 // block N rows
    int NW0, NT;
    if (yb == 0) { NW0 = ng * 48; NT = 6; }
    else         { NW0 = ng ? 40 : 0; NT = ng ? 4 : 5; }
    int b = blockIdx.z;
    int r0 = blockIdx.x * 2;
    int p0 = blockIdx.x * 128;

    float acc[2][6][4];
#pragma unroll
    for (int i = 0; i < 2; i++)
#pragma unroll
        for (int j = 0; j < 6; j++)
#pragma unroll
            for (int q = 0; q < 4; q++) acc[i][j][q] = 0.f;

    int nbt = NB * 12;                     // B staging tasks (hi+lo)
    auto stage = [&](int kc, int sbuf) {
        int tap = kc >> 1, half = kc & 1;
        int ky = tap / 3 - 1, kx = tap % 3 - 1;
        for (int i = tid; i < 1536; i += 256) {
            int buf = i >= 768;
            int r = i - buf * 768;
            int px = r / 6, seg = r - px * 6;
            int row = (px >> 6) + r0 + ky;
            int col = (px & 63) + kx;
            int ok = ((unsigned)row < 64u && (unsigned)col < 64u) ? 16 : 0;
            int rowc = ok ? row : 0, colc = ok ? col : 0;
            const __nv_bfloat16* src = (buf ? g_xtl : g_xth)
                + ((size_t)b * HW + rowc * 64 + colc) * 96 + half * 48 + seg * 8;
            uint32_t dst = sbase + AB(sbuf) + buf * OA_SZ
                + (uint32_t)(px * OST + seg * 8) * 2;
            CP_ASYNC16(dst, src, ok);
        }
        for (int i = tid; i < nbt; i += 256) {
            int buf = i >= NB * 6;
            int r = i - buf * NB * 6;
            int n = r / 6, seg = r - n * 6;
            const __nv_bfloat16* src = (buf ? g_wofl : g_wofh)
                + (size_t)(NBASE + n) * KOF + tap * 96 + half * 48 + seg * 8;
            uint32_t dst = sbase + BB(sbuf) + buf * OB_SZ
                + (uint32_t)(n * OST + seg * 8) * 2;
            CP_ASYNC16(dst, src, 16);
        }
    };

    stage(0, 0); CP_COMMIT();
    stage(1, 1); CP_COMMIT();

    for (int kc = 0; kc < 18; ++kc) {
        int s = kc & 1;
        if (kc < 17) { CP_WAIT(1); } else { CP_WAIT(0); }
        __syncthreads();
#pragma unroll
        for (int ks = 0; ks < 3; ++ks) {
            uint32_t ah[2][4], al[2][4];
            int arow = m0 + (lane & 15);
            int akcol = ks * 16 + (lane >> 4) * 8;
#pragma unroll
            for (int mt = 0; mt < 2; ++mt) {
                uint32_t aaddr = sbase + AB(s) + (uint32_t)(((arow + mt * 16) * OST + akcol) * 2);
                LDSM4(ah[mt], aaddr);
                LDSM4(al[mt], aaddr + OA_SZ);
            }
            int brow = NW0 + (lane & 7);
            int bk = ks * 16 + ((lane >> 3) & 1) * 8;
#pragma unroll 1
            for (int nt = 0; nt < NT; ++nt) {
                uint32_t baddr = sbase + BB(s) + (uint32_t)(((brow + nt * 8) * OST + bk) * 2);
                uint32_t bh[2], bl[2];
                LDSM2(bh, baddr);
                LDSM2(bl, baddr + OB_SZ);
#pragma unroll
                for (int mt = 0; mt < 2; ++mt) {
                    MMA_BF16(acc[mt][nt], ah[mt], bh);
                    MMA_BF16(acc[mt][nt], ah[mt], bl);
                    MMA_BF16(acc[mt][nt], al[mt], bh);
                }
            }
        }
        if (kc + 2 < 18) {
            __syncthreads();
            stage(kc + 2, s); CP_COMMIT();
        }
    }
    __syncthreads();

    // epilogue: per-warp transpose, +bias, write g_off (oc < OCT only)
    float* eps = (float*)(dsm) + w * 8 * 36;
    int pbase = p0 + m0;
    int rq = lane >> 2, cq = (lane & 3) * 2;
#pragma unroll 1
    for (int nt = 0; nt < NT; ++nt) {
#pragma unroll
        for (int mt = 0; mt < 2; ++mt) {
            eps[(cq + 0) * 36 + mt * 16 + rq]     = acc[mt][nt][0];
            eps[(cq + 1) * 36 + mt * 16 + rq]     = acc[mt][nt][1];
            eps[(cq + 0) * 36 + mt * 16 + rq + 8] = acc[mt][nt][2];
            eps[(cq + 1) * 36 + mt * 16 + rq + 8] = acc[mt][nt][3];
        }
        __syncwarp();
#pragma unroll
        for (int oi = 0; oi < 8; ++oi) {
            int oc = NBASE + NW0 + nt * 8 + oi;
            if (oc < OCT) {
                float v = eps[oi * 36 + lane] + g_bo[oc];
                g_off[((size_t)b * OCT + oc) * HW + pbase + lane] = v;
            }
        }
        __syncwarp();
    }
}

// ---------------- K2: FUSED deformable depthwise (all 3 scales) + BN + ReLU ----
#define ZROW 68                 // half2 per row (64 data + 4 zero pad)
#define ZPL  (64 * ZROW)        // 4352 half2 per channel
#define WDS  83                 // 9+25+49 taps per channel
#define DEF_SMEM (6 * ZPL * 4 + 6 * WDS * 4)

template<int KT, int K2T>
__device__ __forceinline__ void run_scale(
    const float* __restrict__ offb, const uint32_t* __restrict__ zp,
    const float* __restrict__ wdw_s, float yf, float xf, float* acc) {
    int t = 0;
#pragma unroll 1
    for (int ty = 0; ty < KT; ++ty) {
        float pny = (float)(ty - (KT - 1) / 2);
#pragma unroll
        for (int tx = 0; tx < KT; ++tx, ++t) {
            float pnx = (float)(tx - (KT - 1) / 2);
            float dy = __ldg(offb + (size_t)t * HW);
            float dx = __ldg(offb + (size_t)(K2T + t) * HW);
            float py = fminf(fmaxf(yf + pny + dy, 0.f), 63.f);
            float px = fminf(fmaxf(xf + pnx + dx, 0.f), 63.f);
            float fy = floorf(py), fx = floorf(px);
            float wy = py - fy, wx = px - fx;
            int idx = (int)fy * ZROW + (int)fx;
            float w1y = 1.f - wy;
            __half2 wxh  = __float2half2_rn(wx);
            __half2 w1xh = __float2half2_rn(1.f - wx);
#pragma unroll
            for (int ci = 0; ci < 6; ci++) {
                uint32_t a  = zp[ci * ZPL + idx];
                uint32_t b2 = zp[ci * ZPL + idx + 1];
                __half2 t2 = __hfma2(wxh, *(__half2*)&b2, __hmul2(w1xh, *(__half2*)&a));
                float2 ft = __half22float2(t2);
                float v = fmaf(wy, ft.y, w1y * ft.x);
                acc[ci] = fmaf(wdw_s[ci * WDS + t], v, acc[ci]);
            }
        }
    }
}

__global__ __launch_bounds__(512) void deform_fused_kernel(
    const float* __restrict__ x,
    const float* __restrict__ wdw3, const float* __restrict__ wdw5,
    const float* __restrict__ wdw7,
    const float* __restrict__ g3, const float* __restrict__ be3,
    const float* __restrict__ m3, const float* __restrict__ v3,
    const float* __restrict__ g5, const float* __restrict__ be5,
    const float* __restrict__ m5, const float* __restrict__ v5,
    const float* __restrict__ g7, const float* __restrict__ be7,
    const float* __restrict__ m7, const float* __restrict__ v7) {
    extern __shared__ char dsm_raw[];
    uint32_t* zp = (uint32_t*)dsm_raw;                 // 6 half2 planes
    float* wdw_s = (float*)(dsm_raw + 6 * ZPL * 4);    // 6 * 83
    int tid = threadIdx.x;
    int b = blockIdx.z;
    int p = blockIdx.x * 512 + tid;
    int cbase = blockIdx.y * 6;
    float yf = (float)(p >> 6), xf = (float)(p & 63);
    const float* xb = x + (size_t)b * C_ * HW;

    for (int i = tid; i < 6 * 64 * 4; i += 512) {
        int ci = i >> 8, r = i & 255;
        int y = r >> 2, c = 64 + (r & 3);
        zp[ci * ZPL + y * ZROW + c] = 0u;
    }
    for (int i = tid; i < 6144; i += 512) {
        int ci = i >> 10, r = i & 1023;
        int y = r >> 4, q = r & 15;
        const float* xp = xb + (size_t)(cbase + ci) * HW;
        float4 cur = *(const float4*)(xp + y * 64 + q * 4);
        float4 nxt = make_float4(0.f, 0.f, 0.f, 0.f);
        if (y < 63) nxt = *(const float4*)(xp + (y + 1) * 64 + q * 4);
        __half2 h0 = __floats2half2_rn(cur.x, nxt.x);
        __half2 h1 = __floats2half2_rn(cur.y, nxt.y);
        __half2 h2 = __floats2half2_rn(cur.z, nxt.z);
        __half2 h3 = __floats2half2_rn(cur.w, nxt.w);
        uint4 ov;
        ov.x = *(uint32_t*)&h0; ov.y = *(uint32_t*)&h1;
        ov.z = *(uint32_t*)&h2; ov.w = *(uint32_t*)&h3;
        *(uint4*)(zp + ci * ZPL + y * ZROW + q * 4) = ov;
    }
    for (int i = tid; i < 6 * WDS; i += 512) {
        int ci = i / WDS, t = i % WDS;
        float v;
        if (t < 9)       v = wdw3[(cbase + ci) * 9 + t];
        else if (t < 34) v = wdw5[(cbase + ci) * 25 + (t - 9)];
        else             v = wdw7[(cbase + ci) * 49 + (t - 34)];
        wdw_s[ci * WDS + t] = v;
    }
    __syncthreads();

    float* row = g_xc + ((size_t)b * HW + p) * KP + cbase;

    {
        float acc[6];
#pragma unroll
        for (int ci = 0; ci < 6; ci++) acc[ci] = 0.f;
        run_scale<3, 9>(g_off + ((size_t)b * OCT + 0) * HW + p, zp, wdw_s, yf, xf, acc);
#pragma unroll
        for (int ci = 0; ci < 6; ci++) {
            int c = cbase + ci;
            float inv = __ldg(g3 + c) * rsqrtf(__ldg(v3 + c) + EPSV);
            float sh  = __ldg(be3 + c) - __ldg(m3 + c) * inv;
            acc[ci] = fmaxf(fmaf(acc[ci], inv, sh), 0.f);
        }
        *(float2*)(row + 0) = make_float2(acc[0], acc[1]);
        *(float2*)(row + 2) = make_float2(acc[2], acc[3]);
        *(float2*)(row + 4) = make_float2(acc[4], acc[5]);
    }
    {
        float acc[6];
#pragma unroll
        for (int ci = 0; ci < 6; ci++) acc[ci] = 0.f;
        run_scale<5, 25>(g_off + ((size_t)b * OCT + 18) * HW + p, zp, wdw_s + 9, yf, xf, acc);
#pragma unroll
        for (int ci = 0; ci < 6; ci++) {
            int c = cbase + ci;
            float inv = __ldg(g5 + c) * rsqrtf(__ldg(v5 + c) + EPSV);
            float sh  = __ldg(be5 + c) - __ldg(m5 + c) * inv;
            acc[ci] = fmaxf(fmaf(acc[ci], inv, sh), 0.f);
        }
        *(float2*)(row + 96 + 0) = make_float2(acc[0], acc[1]);
        *(float2*)(row + 96 + 2) = make_float2(acc[2], acc[3]);
        *(float2*)(row + 96 + 4) = make_float2(acc[4], acc[5]);
    }
    {
        float acc[6];
#pragma unroll
        for (int ci = 0; ci < 6; ci++) acc[ci] = 0.f;
        run_scale<7, 49>(g_off + ((size_t)b * OCT + 68) * HW + p, zp, wdw_s + 34, yf, xf, acc);
#pragma unroll
        for (int ci = 0; ci < 6; ci++) {
            int c = cbase + ci;
            float inv = __ldg(g7 + c) * rsqrtf(__ldg(v7 + c) + EPSV);
            float sh  = __ldg(be7 + c) - __ldg(m7 + c) * inv;
            acc[ci] = fmaxf(fmaf(acc[ci], inv, sh), 0.f);
        }
        *(float2*)(row + 192 + 0) = make_float2(acc[0], acc[1]);
        *(float2*)(row + 192 + 2) = make_float2(acc[2], acc[3]);
        *(float2*)(row + 192 + 4) = make_float2(acc[4], acc[5]);
    }
}

// ---------------- K3: pointwise GEMM via mma.sync bf16 2-split + BN + ReLU ----
#define ST    56
#define A_HI  0
#define A_LO  14336
#define B_HI  28672
#define B_LO  50176
#define PW_SMEM 71680

__global__ __launch_bounds__(256) void pw_mma_kernel(
    const float* __restrict__ gp, const float* __restrict__ bp,
    const float* __restrict__ mp, const float* __restrict__ vp,
    float* __restrict__ out) {
    extern __shared__ char dsm[];
    uint32_t sbase = smem_u32(dsm);
    int tid = threadIdx.x, w = tid >> 5, lane = tid & 31;
    int m0 = (w & 3) * 32, n0 = (w >> 2) * 96;
    int P0 = blockIdx.x * 128;
    const float* xrow = g_xc + (size_t)P0 * KP;

    float acc[2][12][4];
#pragma unroll
    for (int i = 0; i < 2; i++)
#pragma unroll
        for (int j = 0; j < 12; j++)
#pragma unroll
            for (int q = 0; q < 4; q++) acc[i][j][q] = 0.f;

    for (int kc = 0; kc < 9; ++kc) {
        __syncthreads();
        for (int i = tid; i < 1024; i += 256) {
            int px = i >> 3, k4 = (i & 7) * 4;
            float4 v = *(const float4*)(xrow + (size_t)px * KP + kc * 32 + k4);
            __nv_bfloat16 h0 = __float2bfloat16(v.x), h1 = __float2bfloat16(v.y);
            __nv_bfloat16 h2 = __float2bfloat16(v.z), h3 = __float2bfloat16(v.w);
            __nv_bfloat16 l0 = __float2bfloat16(v.x - __bfloat162float(h0));
            __nv_bfloat16 l1 = __float2bfloat16(v.y - __bfloat162float(h1));
            __nv_bfloat16 l2 = __float2bfloat16(v.z - __bfloat162float(h2));
            __nv_bfloat16 l3 = __float2bfloat16(v.w - __bfloat162float(h3));
            uint2 hv, lv;
            hv.x = ((uint32_t)__bfloat16_as_ushort(h1) << 16) | __bfloat16_as_ushort(h0);
            hv.y = ((uint32_t)__bfloat16_as_ushort(h3) << 16) | __bfloat16_as_ushort(h2);
            lv.x = ((uint32_t)__bfloat16_as_ushort(l1) << 16) | __bfloat16_as_ushort(l0);
            lv.y = ((uint32_t)__bfloat16_as_ushort(l3) << 16) | __bfloat16_as_ushort(l2);
            int off = (px * ST + k4) * 2;
            *(uint2*)(dsm + A_HI + off) = hv;
            *(uint2*)(dsm + A_LO + off) = lv;
        }
        for (int i = tid; i < 3072; i += 256) {
            int buf = i >= 1536;
            int r = i - buf * 1536;
            int n = r >> 3, k4 = (r & 7) * 4;
            uint2 v = *(const uint2*)((buf ? g_pwl : g_pwh) + n * KP + kc * 32 + k4);
            *(uint2*)(dsm + (buf ? B_LO : B_HI) + (n * ST + k4) * 2) = v;
        }
        __syncthreads();

#pragma unroll
        for (int ks = 0; ks < 2; ++ks) {
            uint32_t ah[2][4], al[2][4];
            int arow = m0 + (lane & 15);
            int akcol = ks * 16 + (lane >> 4) * 8;
#pragma unroll
            for (int mt = 0; mt < 2; ++mt) {
                uint32_t aaddr = sbase + A_HI + (uint32_t)(((arow + mt * 16) * ST + akcol) * 2);
                LDSM4(ah[mt], aaddr);
                LDSM4(al[mt], aaddr + (A_LO - A_HI));
            }
            int brow = n0 + (lane & 7);
            int bk = ks * 16 + ((lane >> 3) & 1) * 8;
#pragma unroll
            for (int nt = 0; nt < 12; ++nt) {
                uint32_t baddr = sbase + B_HI + (uint32_t)(((brow + nt * 8) * ST + bk) * 2);
                uint32_t bh[2], bl[2];
                LDSM2(bh, baddr);
                LDSM2(bl, baddr + (B_LO - B_HI));
#pragma unroll
                for (int mt = 0; mt < 2; ++mt) {
                    MMA_BF16(acc[mt][nt], ah[mt], bh);
                    MMA_BF16(acc[mt][nt], ah[mt], bl);
                    MMA_BF16(acc[mt][nt], al[mt], bh);
                }
            }
        }
    }
    __syncthreads();

    float* eps = (float*)(dsm) + w * 8 * 36;
    int b = P0 >> 12;
    int pbase = (P0 & 4095) + m0;
    int rq = lane >> 2, cq = (lane & 3) * 2;
#pragma unroll 1
    for (int nt = 0; nt < 12; ++nt) {
#pragma unroll
        for (int mt = 0; mt < 2; ++mt) {
            eps[(cq + 0) * 36 + mt * 16 + rq]     = acc[mt][nt][0];
            eps[(cq + 1) * 36 + mt * 16 + rq]     = acc[mt][nt][1];
            eps[(cq + 0) * 36 + mt * 16 + rq + 8] = acc[mt][nt][2];
            eps[(cq + 1) * 36 + mt * 16 + rq + 8] = acc[mt][nt][3];
        }
        __syncwarp();
#pragma unroll
        for (int oi = 0; oi < 8; ++oi) {
            int oc = n0 + nt * 8 + oi;
            float inv = __ldg(gp + oc) * rsqrtf(__ldg(vp + oc) + EPSV);
            float sh  = __ldg(bp + oc) - __ldg(mp + oc) * inv;
            float v = eps[oi * 36 + lane];
            out[((size_t)b * O_ + oc) * HW + pbase + lane] = fmaxf(fmaf(v, inv, sh), 0.f);
        }
        __syncwarp();
    }
}

// ---------------- launch ------------------------------------------------------
extern "C" void kernel_launch(void* const* d_in, const int* in_sizes, int n_in,
                              void* d_out, int out_size) {
    const float* x     = (const float*)d_in[0];
    const float* w3    = (const float*)d_in[1];
    const float* b3    = (const float*)d_in[2];
    const float* wdw3  = (const float*)d_in[3];
    const float* g3    = (const float*)d_in[4];
    const float* be3   = (const float*)d_in[5];
    const float* m3    = (const float*)d_in[6];
    const float* v3    = (const float*)d_in[7];
    const float* w5    = (const float*)d_in[8];
    const float* b5    = (const float*)d_in[9];
    const float* wdw5  = (const float*)d_in[10];
    const float* g5    = (const float*)d_in[11];
    const float* be5   = (const float*)d_in[12];
    const float* m5    = (const float*)d_in[13];
    const float* v5    = (const float*)d_in[14];
    const float* w7    = (const float*)d_in[15];
    const float* b7    = (const float*)d_in[16];
    const float* wdw7  = (const float*)d_in[17];
    const float* g7    = (const float*)d_in[18];
    const float* be7   = (const float*)d_in[19];
    const float* m7    = (const float*)d_in[20];
    const float* v7    = (const float*)d_in[21];
    const float* wpw   = (const float*)d_in[22];
    const float* gp    = (const float*)d_in[23];
    const float* bp    = (const float*)d_in[24];
    const float* mp    = (const float*)d_in[25];
    const float* vp    = (const float*)d_in[26];
    float* out = (float*)d_out;

    cudaFuncSetAttribute(deform_fused_kernel,
                         cudaFuncAttributeMaxDynamicSharedMemorySize, DEF_SMEM);
    cudaFuncSetAttribute(pw_mma_kernel,
                         cudaFuncAttributeMaxDynamicSharedMemorySize, PW_SMEM);
    cudaFuncSetAttribute(offconv_mma_kernel,
                         cudaFuncAttributeMaxDynamicSharedMemorySize, OFF_SMEM);

    prep_kernel<<<256, 256>>>(w3, b3, w5, b5, w7, b7, wpw);
    xpose_kernel<<<256, 256>>>(x);
    offconv_mma_kernel<<<dim3(32, 2, B_), 256, OFF_SMEM>>>();
    deform_fused_kernel<<<dim3(8, 16, B_), 512, DEF_SMEM>>>(
        x, wdw3, wdw5, wdw7,
        g3, be3, m3, v3, g5, be5, m5, v5, g7, be7, m7, v7);
    pw_mma_kernel<<<128, 256, PW_SMEM>>>(gp, bp, mp, vp, out);
}

// round 17
// speedup vs baseline: 1.7735x; 1.7735x over previous
#include <cuda_runtime.h>
#include <cuda_bf16.h>
#include <cuda_fp16.h>
#include <cstdint>

#define EPSV 1e-5f
#define B_   4
#define C_   96
#define HW   4096
#define OCT  166     // 18 + 50 + 98 offset channels
#define OCP  192     // weight-pack padding
#define KOF  864     // 9*96 offset-conv K
#define KP   320     // g_xc row stride (288 used)
#define O_   192

// ---------------- scratch (static device globals) -----------------------------
__device__ float g_off[B_ * OCT * HW];          // offset conv output  [b][oc][p]
__device__ float g_xc [B_ * HW * KP];           // deform output, PIXEL-major [b*HW+p][KP]
__device__ float g_bo [OCP];                    // packed offset bias
__device__ __nv_bfloat16 g_xth[B_ * HW * 96];   // x transposed hi [b*HW+p][c]
__device__ __nv_bfloat16 g_xtl[B_ * HW * 96];   // x transposed lo
__device__ __nv_bfloat16 g_wofh[OCP * KOF];     // offset weights hi [oc][tap*96+c]
__device__ __nv_bfloat16 g_wofl[OCP * KOF];     // offset weights lo
__device__ __nv_bfloat16 g_pwh[O_ * KP];        // pointwise weights hi [o][KP]
__device__ __nv_bfloat16 g_pwl[O_ * KP];        // pointwise weights lo [o][KP]

__device__ __forceinline__ uint32_t smem_u32(const void* p) {
    uint32_t a;
    asm("{ .reg .u64 t; cvta.to.shared.u64 t, %1; cvt.u32.u64 %0, t; }" : "=r"(a) : "l"(p));
    return a;
}
#define LDSM4(r, addr) \
    asm volatile("ldmatrix.sync.aligned.m8n8.x4.shared.b16 {%0,%1,%2,%3}, [%4];" \
        : "=r"((r)[0]), "=r"((r)[1]), "=r"((r)[2]), "=r"((r)[3]) : "r"(addr))
#define LDSM2(r, addr) \
    asm volatile("ldmatrix.sync.aligned.m8n8.x2.shared.b16 {%0,%1}, [%2];" \
        : "=r"((r)[0]), "=r"((r)[1]) : "r"(addr))
#define MMA_BF16(d, a, b) \
    asm volatile("mma.sync.aligned.m16n8k16.row.col.f32.bf16.bf16.f32 " \
        "{%0,%1,%2,%3}, {%4,%5,%6,%7}, {%8,%9}, {%0,%1,%2,%3};" \
        : "+f"((d)[0]), "+f"((d)[1]), "+f"((d)[2]), "+f"((d)[3]) \
        : "r"((a)[0]), "r"((a)[1]), "r"((a)[2]), "r"((a)[3]), "r"((b)[0]), "r"((b)[1]))
#define CP_ASYNC16(dst, src, n) \
    asm volatile("cp.async.cg.shared.global [%0], [%1], 16, %2;" \
        :: "r"(dst), "l"(src), "r"(n))
#define CP_COMMIT() asm volatile("cp.async.commit_group;" ::: "memory")
#define CP_WAIT(N)  asm volatile("cp.async.wait_group %0;" :: "n"(N) : "memory")

// ---------------- prep: pack + bf16-split weights -----------------------------
__global__ void prep_kernel(const float* __restrict__ w3, const float* __restrict__ b3,
                            const float* __restrict__ w5, const float* __restrict__ b5,
                            const float* __restrict__ w7, const float* __restrict__ b7,
                            const float* __restrict__ wpw) {
    int i0 = blockIdx.x * blockDim.x + threadIdx.x;
    int stride = gridDim.x * blockDim.x;
    for (int idx = i0; idx < OCP * KOF; idx += stride) {
        int oc = idx / KOF, k = idx % KOF;
        int r = k / 96, c = k % 96;
        float v = 0.f;
        if (oc < 18)        v = w3[(oc * C_ + c) * 9 + r];
        else if (oc < 68)   v = w5[((oc - 18) * C_ + c) * 9 + r];
        else if (oc < OCT)  v = w7[((oc - 68) * C_ + c) * 9 + r];
        __nv_bfloat16 h = __float2bfloat16(v);
        g_wofh[idx] = h;
        g_wofl[idx] = __float2bfloat16(v - __bfloat162float(h));
    }
    for (int idx = i0; idx < OCP; idx += stride) {
        float v = 0.f;
        if (idx < 18)       v = b3[idx];
        else if (idx < 68)  v = b5[idx - 18];
        else if (idx < OCT) v = b7[idx - 68];
        g_bo[idx] = v;
    }
    for (int idx = i0; idx < O_ * KP; idx += stride) {
        int n = idx / KP, k = idx % KP;
        float w = (k < 288) ? wpw[n * 288 + k] : 0.f;
        __nv_bfloat16 h = __float2bfloat16(w);
        g_pwh[idx] = h;
        g_pwl[idx] = __float2bfloat16(w - __bfloat162float(h));
    }
}

// ---------------- xpose: x [b][c][p] -> pixel-major bf16 hi/lo (coalesced) -----
__global__ __launch_bounds__(256) void xpose_kernel(const float* __restrict__ x) {
    __shared__ float st[64][97];
    int tid = threadIdx.x;
    int g0 = blockIdx.x * 64;              // global pixel index (b*HW+p)
    int b = g0 >> 12, p0 = g0 & 4095;
    const float* src = x + (size_t)b * C_ * HW + p0;
    for (int i = tid; i < 96 * 64; i += 256) {
        int c = i >> 6, px = i & 63;
        st[px][c] = src[(size_t)c * HW + px];
    }
    __syncthreads();
    for (int i = tid; i < 64 * 12; i += 256) {
        int px = i / 12, seg = i - px * 12;
        __nv_bfloat16 h8[8], l8[8];
#pragma unroll
        for (int j = 0; j < 8; ++j) {
            float v = st[px][seg * 8 + j];
            h8[j] = __float2bfloat16(v);
            l8[j] = __float2bfloat16(v - __bfloat162float(h8[j]));
        }
        size_t o = (size_t)(g0 + px) * 96 + seg * 8;
        *(uint4*)(g_xth + o) = *(uint4*)h8;
        *(uint4*)(g_xtl + o) = *(uint4*)l8;
    }
}

// ---------------- K1: offset conv, HMMA implicit GEMM + cp.async pipeline ------
// grid (32 pixel-tiles of 128 px, 1, 4 batch), 256 threads = 8 warps (4M x 2N).
// M=128 px, N=168 oc (12/9 nt split, both fully unrolled), K chunk = 48 ch.
#define OST   56                           // bf16 per smem row (112 B)
#define OA_SZ 14336                        // one A buf half (128*56*2)
#define OB_SZ 18816                        // one B buf half (168*56*2)
#define AB(s)  ((s) * 2 * OA_SZ)
#define BB(s)  (4 * OA_SZ + (s) * 2 * OB_SZ)
#define OFF_SMEM (4 * OA_SZ + 4 * OB_SZ)   // 132608

// fully-unrolled nt loop (templated NT -> independent acc chains interleave)
template<int NT>
__device__ __forceinline__ void do_mmas(
    uint32_t bbase, int brow, int bk,
    uint32_t ah[2][4], uint32_t al[2][4], float (*acc)[4]) {
#pragma unroll
    for (int nt = 0; nt < NT; ++nt) {
        uint32_t baddr = bbase + (uint32_t)(((brow + nt * 8) * OST + bk) * 2);
        uint32_t bh[2], bl[2];
        LDSM2(bh, baddr);
        LDSM2(bl, baddr + OB_SZ);
        MMA_BF16(acc[0 * 12 + nt], ah[0], bh);
        MMA_BF16(acc[1 * 12 + nt], ah[1], bh);
        MMA_BF16(acc[0 * 12 + nt], ah[0], bl);
        MMA_BF16(acc[1 * 12 + nt], ah[1], bl);
        MMA_BF16(acc[0 * 12 + nt], al[0], bh);
        MMA_BF16(acc[1 * 12 + nt], al[1], bh);
    }
}

__global__ __launch_bounds__(256) void offconv_mma_kernel() {
    extern __shared__ char dsm[];
    uint32_t sbase = smem_u32(dsm);
    int tid = threadIdx.x, w = tid >> 5, lane = tid & 31;
    int m0 = (w & 3) * 32;
    int ng = w >> 2, n0 = ng * 96;
    int NT = ng ? 9 : 12;
    int b = blockIdx.z;
    int r0 = blockIdx.x * 2;
    int p0 = blockIdx.x * 128;

    float acc[2 * 12][4];
#pragma unroll
    for (int j = 0; j < 24; j++)
#pragma unroll
        for (int q = 0; q < 4; q++) acc[j][q] = 0.f;

    auto stage = [&](int kc, int sbuf) {
        int tap = kc >> 1, half = kc & 1;
        int ky = tap / 3 - 1, kx = tap % 3 - 1;
        for (int i = tid; i < 1536; i += 256) {
            int buf = i >= 768;
            int r = i - buf * 768;
            int px = r / 6, seg = r - px * 6;
            int row = (px >> 6) + r0 + ky;
            int col = (px & 63) + kx;
            int ok = ((unsigned)row < 64u && (unsigned)col < 64u) ? 16 : 0;
            int rowc = ok ? row : 0, colc = ok ? col : 0;
            const __nv_bfloat16* src = (buf ? g_xtl : g_xth)
                + ((size_t)b * HW + rowc * 64 + colc) * 96 + half * 48 + seg * 8;
            uint32_t dst = sbase + AB(sbuf) + buf * OA_SZ
                + (uint32_t)(px * OST + seg * 8) * 2;
            CP_ASYNC16(dst, src, ok);
        }
        for (int i = tid; i < 2016; i += 256) {
            int buf = i >= 1008;
            int r = i - buf * 1008;
            int n = r / 6, seg = r - n * 6;
            const __nv_bfloat16* src = (buf ? g_wofl : g_wofh)
                + (size_t)n * KOF + tap * 96 + half * 48 + seg * 8;
            uint32_t dst = sbase + BB(sbuf) + buf * OB_SZ
                + (uint32_t)(n * OST + seg * 8) * 2;
            CP_ASYNC16(dst, src, 16);
        }
    };

    stage(0, 0); CP_COMMIT();
    stage(1, 1); CP_COMMIT();

    for (int kc = 0; kc < 18; ++kc) {
        int s = kc & 1;
        if (kc < 17) { CP_WAIT(1); } else { CP_WAIT(0); }
        __syncthreads();
#pragma unroll
        for (int ks = 0; ks < 3; ++ks) {
            uint32_t ah[2][4], al[2][4];
            int arow = m0 + (lane & 15);
            int akcol = ks * 16 + (lane >> 4) * 8;
#pragma unroll
            for (int mt = 0; mt < 2; ++mt) {
                uint32_t aaddr = sbase + AB(s) + (uint32_t)(((arow + mt * 16) * OST + akcol) * 2);
                LDSM4(ah[mt], aaddr);
                LDSM4(al[mt], aaddr + OA_SZ);
            }
            int brow = n0 + (lane & 7);
            int bk = ks * 16 + ((lane >> 3) & 1) * 8;
            uint32_t bbase = sbase + BB(s);
            if (ng == 0) do_mmas<12>(bbase, brow, bk, ah, al, acc);
            else         do_mmas<9>(bbase, brow, bk, ah, al, acc);
        }
        if (kc + 2 < 18) {
            __syncthreads();
            stage(kc + 2, s); CP_COMMIT();
        }
    }
    __syncthreads();

    // epilogue: per-warp transpose, +bias, write g_off (oc < OCT only)
    float* eps = (float*)(dsm) + w * 8 * 36;
    int pbase = p0 + m0;
    int rq = lane >> 2, cq = (lane & 3) * 2;
#pragma unroll 1
    for (int nt = 0; nt < NT; ++nt) {
#pragma unroll
        for (int mt = 0; mt < 2; ++mt) {
            eps[(cq + 0) * 36 + mt * 16 + rq]     = acc[mt * 12 + nt][0];
            eps[(cq + 1) * 36 + mt * 16 + rq]     = acc[mt * 12 + nt][1];
            eps[(cq + 0) * 36 + mt * 16 + rq + 8] = acc[mt * 12 + nt][2];
            eps[(cq + 1) * 36 + mt * 16 + rq + 8] = acc[mt * 12 + nt][3];
        }
        __syncwarp();
#pragma unroll
        for (int oi = 0; oi < 8; ++oi) {
            int oc = n0 + nt * 8 + oi;
            if (oc < OCT) {
                float v = eps[oi * 36 + lane] + g_bo[oc];
                g_off[((size_t)b * OCT + oc) * HW + pbase + lane] = v;
            }
        }
        __syncwarp();
    }
}

// ---------------- K2: FUSED deformable depthwise (all 3 scales) + BN + ReLU ----
#define ZROW 68                 // half2 per row (64 data + 4 zero pad)
#define ZPL  (64 * ZROW)        // 4352 half2 per channel
#define WDS  83                 // 9+25+49 taps per channel
#define DEF_SMEM (6 * ZPL * 4 + 6 * WDS * 4)

template<int KT, int K2T>
__device__ __forceinline__ void run_scale(
    const float* __restrict__ offb, const uint32_t* __restrict__ zp,
    const float* __restrict__ wdw_s, float yf, float xf, float* acc) {
    int t = 0;
#pragma unroll 1
    for (int ty = 0; ty < KT; ++ty) {
        float pny = (float)(ty - (KT - 1) / 2);
#pragma unroll
        for (int tx = 0; tx < KT; ++tx, ++t) {
            float pnx = (float)(tx - (KT - 1) / 2);
            float dy = __ldg(offb + (size_t)t * HW);
            float dx = __ldg(offb + (size_t)(K2T + t) * HW);
            float py = fminf(fmaxf(yf + pny + dy, 0.f), 63.f);
            float px = fminf(fmaxf(xf + pnx + dx, 0.f), 63.f);
            float fy = floorf(py), fx = floorf(px);
            float wy = py - fy, wx = px - fx;
            int idx = (int)fy * ZROW + (int)fx;
            float w1y = 1.f - wy;
            __half2 wxh  = __float2half2_rn(wx);
            __half2 w1xh = __float2half2_rn(1.f - wx);
#pragma unroll
            for (int ci = 0; ci < 6; ci++) {
                uint32_t a  = zp[ci * ZPL + idx];
                uint32_t b2 = zp[ci * ZPL + idx + 1];
                __half2 t2 = __hfma2(wxh, *(__half2*)&b2, __hmul2(w1xh, *(__half2*)&a));
                float2 ft = __half22float2(t2);
                float v = fmaf(wy, ft.y, w1y * ft.x);
                acc[ci] = fmaf(wdw_s[ci * WDS + t], v, acc[ci]);
            }
        }
    }
}

__global__ __launch_bounds__(512) void deform_fused_kernel(
    const float* __restrict__ x,
    const float* __restrict__ wdw3, const float* __restrict__ wdw5,
    const float* __restrict__ wdw7,
    const float* __restrict__ g3, const float* __restrict__ be3,
    const float* __restrict__ m3, const float* __restrict__ v3,
    const float* __restrict__ g5, const float* __restrict__ be5,
    const float* __restrict__ m5, const float* __restrict__ v5,
    const float* __restrict__ g7, const float* __restrict__ be7,
    const float* __restrict__ m7, const float* __restrict__ v7) {
    extern __shared__ char dsm_raw[];
    uint32_t* zp = (uint32_t*)dsm_raw;                 // 6 half2 planes
    float* wdw_s = (float*)(dsm_raw + 6 * ZPL * 4);    // 6 * 83
    int tid = threadIdx.x;
    int b = blockIdx.z;
    int p = blockIdx.x * 512 + tid;
    int cbase = blockIdx.y * 6;
    float yf = (float)(p >> 6), xf = (float)(p & 63);
    const float* xb = x + (size_t)b * C_ * HW;

    for (int i = tid; i < 6 * 64 * 4; i += 512) {
        int ci = i >> 8, r = i & 255;
        int y = r >> 2, c = 64 + (r & 3);
        zp[ci * ZPL + y * ZROW + c] = 0u;
    }
    for (int i = tid; i < 6144; i += 512) {
        int ci = i >> 10, r = i & 1023;
        int y = r >> 4, q = r & 15;
        const float* xp = xb + (size_t)(cbase + ci) * HW;
        float4 cur = *(const float4*)(xp + y * 64 + q * 4);
        float4 nxt = make_float4(0.f, 0.f, 0.f, 0.f);
        if (y < 63) nxt = *(const float4*)(xp + (y + 1) * 64 + q * 4);
        __half2 h0 = __floats2half2_rn(cur.x, nxt.x);
        __half2 h1 = __floats2half2_rn(cur.y, nxt.y);
        __half2 h2 = __floats2half2_rn(cur.z, nxt.z);
        __half2 h3 = __floats2half2_rn(cur.w, nxt.w);
        uint4 ov;
        ov.x = *(uint32_t*)&h0; ov.y = *(uint32_t*)&h1;
        ov.z = *(uint32_t*)&h2; ov.w = *(uint32_t*)&h3;
        *(uint4*)(zp + ci * ZPL + y * ZROW + q * 4) = ov;
    }
    for (int i = tid; i < 6 * WDS; i += 512) {
        int ci = i / WDS, t = i % WDS;
        float v;
        if (t < 9)       v = wdw3[(cbase + ci) * 9 + t];
        else if (t < 34) v = wdw5[(cbase + ci) * 25 + (t - 9)];
        else             v = wdw7[(cbase + ci) * 49 + (t - 34)];
        wdw_s[ci * WDS + t] = v;
    }
    __syncthreads();

    float* row = g_xc + ((size_t)b * HW + p) * KP + cbase;

    {
        float acc[6];
#pragma unroll
        for (int ci = 0; ci < 6; ci++) acc[ci] = 0.f;
        run_scale<3, 9>(g_off + ((size_t)b * OCT + 0) * HW + p, zp, wdw_s, yf, xf, acc);
#pragma unroll
        for (int ci = 0; ci < 6; ci++) {
            int c = cbase + ci;
            float inv = __ldg(g3 + c) * rsqrtf(__ldg(v3 + c) + EPSV);
            float sh  = __ldg(be3 + c) - __ldg(m3 + c) * inv;
            acc[ci] = fmaxf(fmaf(acc[ci], inv, sh), 0.f);
        }
        *(float2*)(row + 0) = make_float2(acc[0], acc[1]);
        *(float2*)(row + 2) = make_float2(acc[2], acc[3]);
        *(float2*)(row + 4) = make_float2(acc[4], acc[5]);
    }
    {
        float acc[6];
#pragma unroll
        for (int ci = 0; ci < 6; ci++) acc[ci] = 0.f;
        run_scale<5, 25>(g_off + ((size_t)b * OCT + 18) * HW + p, zp, wdw_s + 9, yf, xf, acc);
#pragma unroll
        for (int ci = 0; ci < 6; ci++) {
            int c = cbase + ci;
            float inv = __ldg(g5 + c) * rsqrtf(__ldg(v5 + c) + EPSV);
            float sh  = __ldg(be5 + c) - __ldg(m5 + c) * inv;
            acc[ci] = fmaxf(fmaf(acc[ci], inv, sh), 0.f);
        }
        *(float2*)(row + 96 + 0) = make_float2(acc[0], acc[1]);
        *(float2*)(row + 96 + 2) = make_float2(acc[2], acc[3]);
        *(float2*)(row + 96 + 4) = make_float2(acc[4], acc[5]);
    }
    {
        float acc[6];
#pragma unroll
        for (int ci = 0; ci < 6; ci++) acc[ci] = 0.f;
        run_scale<7, 49>(g_off + ((size_t)b * OCT + 68) * HW + p, zp, wdw_s + 34, yf, xf, acc);
#pragma unroll
        for (int ci = 0; ci < 6; ci++) {
            int c = cbase + ci;
            float inv = __ldg(g7 + c) * rsqrtf(__ldg(v7 + c) + EPSV);
            float sh  = __ldg(be7 + c) - __ldg(m7 + c) * inv;
            acc[ci] = fmaxf(fmaf(acc[ci], inv, sh), 0.f);
        }
        *(float2*)(row + 192 + 0) = make_float2(acc[0], acc[1]);
        *(float2*)(row + 192 + 2) = make_float2(acc[2], acc[3]);
        *(float2*)(row + 192 + 4) = make_float2(acc[4], acc[5]);
    }
}

// ---------------- K3: pointwise GEMM via mma.sync bf16 2-split + BN + ReLU ----
#define ST    56
#define A_HI  0
#define A_LO  14336
#define B_HI  28672
#define B_LO  50176
#define PW_SMEM 71680

__global__ __launch_bounds__(256) void pw_mma_kernel(
    const float* __restrict__ gp, const float* __restrict__ bp,
    const float* __restrict__ mp, const float* __restrict__ vp,
    float* __restrict__ out) {
    extern __shared__ char dsm[];
    uint32_t sbase = smem_u32(dsm);
    int tid = threadIdx.x, w = tid >> 5, lane = tid & 31;
    int m0 = (w & 3) * 32, n0 = (w >> 2) * 96;
    int P0 = blockIdx.x * 128;
    const float* xrow = g_xc + (size_t)P0 * KP;

    float acc[2][12][4];
#pragma unroll
    for (int i = 0; i < 2; i++)
#pragma unroll
        for (int j = 0; j < 12; j++)
#pragma unroll
            for (int q = 0; q < 4; q++) acc[i][j][q] = 0.f;

    for (int kc = 0; kc < 9; ++kc) {
        __syncthreads();
        for (int i = tid; i < 1024; i += 256) {
            int px = i >> 3, k4 = (i & 7) * 4;
            float4 v = *(const float4*)(xrow + (size_t)px * KP + kc * 32 + k4);
            __nv_bfloat16 h0 = __float2bfloat16(v.x), h1 = __float2bfloat16(v.y);
            __nv_bfloat16 h2 = __float2bfloat16(v.z), h3 = __float2bfloat16(v.w);
            __nv_bfloat16 l0 = __float2bfloat16(v.x - __bfloat162float(h0));
            __nv_bfloat16 l1 = __float2bfloat16(v.y - __bfloat162float(h1));
            __nv_bfloat16 l2 = __float2bfloat16(v.z - __bfloat162float(h2));
            __nv_bfloat16 l3 = __float2bfloat16(v.w - __bfloat162float(h3));
            uint2 hv, lv;
            hv.x = ((uint32_t)__bfloat16_as_ushort(h1) << 16) | __bfloat16_as_ushort(h0);
            hv.y = ((uint32_t)__bfloat16_as_ushort(h3) << 16) | __bfloat16_as_ushort(h2);
            lv.x = ((uint32_t)__bfloat16_as_ushort(l1) << 16) | __bfloat16_as_ushort(l0);
            lv.y = ((uint32_t)__bfloat16_as_ushort(l3) << 16) | __bfloat16_as_ushort(l2);
            int off = (px * ST + k4) * 2;
            *(uint2*)(dsm + A_HI + off) = hv;
            *(uint2*)(dsm + A_LO + off) = lv;
        }
        for (int i = tid; i < 3072; i += 256) {
            int buf = i >= 1536;
            int r = i - buf * 1536;
            int n = r >> 3, k4 = (r & 7) * 4;
            uint2 v = *(const uint2*)((buf ? g_pwl : g_pwh) + n * KP + kc * 32 + k4);
            *(uint2*)(dsm + (buf ? B_LO : B_HI) + (n * ST + k4) * 2) = v;
        }
        __syncthreads();

#pragma unroll
        for (int ks = 0; ks < 2; ++ks) {
            uint32_t ah[2][4], al[2][4];
            int arow = m0 + (lane & 15);
            int akcol = ks * 16 + (lane >> 4) * 8;
#pragma unroll
            for (int mt = 0; mt < 2; ++mt) {
                uint32_t aaddr = sbase + A_HI + (uint32_t)(((arow + mt * 16) * ST + akcol) * 2);
                LDSM4(ah[mt], aaddr);
                LDSM4(al[mt], aaddr + (A_LO - A_HI));
            }
            int brow = n0 + (lane & 7);
            int bk = ks * 16 + ((lane >> 3) & 1) * 8;
#pragma unroll
            for (int nt = 0; nt < 12; ++nt) {
                uint32_t baddr = sbase + B_HI + (uint32_t)(((brow + nt * 8) * ST + bk) * 2);
                uint32_t bh[2], bl[2];
                LDSM2(bh, baddr);
                LDSM2(bl, baddr + (B_LO - B_HI));
#pragma unroll
                for (int mt = 0; mt < 2; ++mt) {
                    MMA_BF16(acc[mt][nt], ah[mt], bh);
                    MMA_BF16(acc[mt][nt], ah[mt], bl);
                    MMA_BF16(acc[mt][nt], al[mt], bh);
                }
            }
        }
    }
    __syncthreads();

    float* eps = (float*)(dsm) + w * 8 * 36;
    int b = P0 >> 12;
    int pbase = (P0 & 4095) + m0;
    int rq = lane >> 2, cq = (lane & 3) * 2;
#pragma unroll 1
    for (int nt = 0; nt < 12; ++nt) {
#pragma unroll
        for (int mt = 0; mt < 2; ++mt) {
            eps[(cq + 0) * 36 + mt * 16 + rq]     = acc[mt][nt][0];
            eps[(cq + 1) * 36 + mt * 16 + rq]     = acc[mt][nt][1];
            eps[(cq + 0) * 36 + mt * 16 + rq + 8] = acc[mt][nt][2];
            eps[(cq + 1) * 36 + mt * 16 + rq + 8] = acc[mt][nt][3];
        }
        __syncwarp();
#pragma unroll
        for (int oi = 0; oi < 8; ++oi) {
            int oc = n0 + nt * 8 + oi;
            float inv = __ldg(gp + oc) * rsqrtf(__ldg(vp + oc) + EPSV);
            float sh  = __ldg(bp + oc) - __ldg(mp + oc) * inv;
            float v = eps[oi * 36 + lane];
            out[((size_t)b * O_ + oc) * HW + pbase + lane] = fmaxf(fmaf(v, inv, sh), 0.f);
        }
        __syncwarp();
    }
}

// ---------------- launch ------------------------------------------------------
extern "C" void kernel_launch(void* const* d_in, const int* in_sizes, int n_in,
                              void* d_out, int out_size) {
    const float* x     = (const float*)d_in[0];
    const float* w3    = (const float*)d_in[1];
    const float* b3    = (const float*)d_in[2];
    const float* wdw3  = (const float*)d_in[3];
    const float* g3    = (const float*)d_in[4];
    const float* be3   = (const float*)d_in[5];
    const float* m3    = (const float*)d_in[6];
    const float* v3    = (const float*)d_in[7];
    const float* w5    = (const float*)d_in[8];
    const float* b5    = (const float*)d_in[9];
    const float* wdw5  = (const float*)d_in[10];
    const float* g5    = (const float*)d_in[11];
    const float* be5   = (const float*)d_in[12];
    const float* m5    = (const float*)d_in[13];
    const float* v5    = (const float*)d_in[14];
    const float* w7    = (const float*)d_in[15];
    const float* b7    = (const float*)d_in[16];
    const float* wdw7  = (const float*)d_in[17];
    const float* g7    = (const float*)d_in[18];
    const float* be7   = (const float*)d_in[19];
    const float* m7    = (const float*)d_in[20];
    const float* v7    = (const float*)d_in[21];
    const float* wpw   = (const float*)d_in[22];
    const float* gp    = (const float*)d_in[23];
    const float* bp    = (const float*)d_in[24];
    const float* mp    = (const float*)d_in[25];
    const float* vp    = (const float*)d_in[26];
    float* out = (float*)d_out;

    cudaFuncSetAttribute(deform_fused_kernel,
                         cudaFuncAttributeMaxDynamicSharedMemorySize, DEF_SMEM);
    cudaFuncSetAttribute(pw_mma_kernel,
                         cudaFuncAttributeMaxDynamicSharedMemorySize, PW_SMEM);
    cudaFuncSetAttribute(offconv_mma_kernel,
                         cudaFuncAttributeMaxDynamicSharedMemorySize, OFF_SMEM);

    prep_kernel<<<256, 256>>>(w3, b3, w5, b5, w7, b7, wpw);
    xpose_kernel<<<256, 256>>>(x);
    offconv_mma_kernel<<<dim3(32, 1, B_), 256, OFF_SMEM>>>();
    deform_fused_kernel<<<dim3(8, 16, B_), 512, DEF_SMEM>>>(
        x, wdw3, wdw5, wdw7,
        g3, be3, m3, v3, g5, be5, m5, v5, g7, be7, m7, v7);
    pw_mma_kernel<<<128, 256, PW_SMEM>>>(gp, bp, mp, vp, out);
}